// round 15
// baseline (speedup 1.0000x reference)
#include <cuda_runtime.h>
#include <cstdint>

// Fixed-shape problem: pred (B=32, 24, 160, 160) fp32, targets (N=512, 6)
#define HGT   160
#define WID   160
#define HW    (HGT * WID)            // 25600
#define NANCH 3
#define NCLS  3
#define NCH   24

#define NTHREADS   256
#define PLANE_B    (HW * 4)          // 102400 bytes per conf plane
#define NSTAGE     5                 // whole plane resident: 5 x 20KB
#define CHUNK_B    20480
#define CHUNK_F4   (CHUNK_B / 16)    // 1280 float4
#define SMEM_DYN   (NSTAGE * CHUNK_B)   // 102400 bytes
#define MAX_TGT    2048
#define MAX_SPB    64
#define MAX_LOCAL  16

// Scratch (device globals; no allocation allowed). Overwritten every call.
__device__ float g_partials[NANCH * 64];     // one per conf plane (<=192)
__device__ float g_sparse[MAX_SPB][4];       // {sbox, scls, scorr, count}
__device__ int   g_count = 0;                // reset by fold block each launch

__device__ __forceinline__ float tanh_fast(float x) {
    float r;
    asm("tanh.approx.f32 %0, %1;" : "=f"(r) : "f"(x));
    return r;
}
// sigmoid(x) = 0.5*tanh(0.5x) + 0.5   (one MUFU op)
__device__ __forceinline__ float sig_fast(float x) {
    return fmaf(0.5f, tanh_fast(0.5f * x), 0.5f);
}

__device__ __forceinline__ uint32_t smem_u32(const void* p) {
    return (uint32_t)__cvta_generic_to_shared(p);
}
__device__ __forceinline__ void mbar_init(uint32_t mbar, uint32_t cnt) {
    asm volatile("mbarrier.init.shared.b64 [%0], %1;" :: "r"(mbar), "r"(cnt) : "memory");
}
__device__ __forceinline__ void mbar_expect_tx(uint32_t mbar, uint32_t bytes) {
    asm volatile("mbarrier.arrive.expect_tx.shared.b64 _, [%0], %1;"
                 :: "r"(mbar), "r"(bytes) : "memory");
}
__device__ __forceinline__ void mbar_wait(uint32_t mbar, uint32_t parity) {
    asm volatile(
        "{\n\t"
        ".reg .pred P;\n\t"
        "WAIT_%=:\n\t"
        "mbarrier.try_wait.parity.acquire.cta.shared::cta.b64 P, [%0], %1, 0x989680;\n\t"
        "@P bra.uni DONE_%=;\n\t"
        "bra.uni WAIT_%=;\n\t"
        "DONE_%=:\n\t"
        "}"
        :: "r"(mbar), "r"(parity) : "memory");
}
__device__ __forceinline__ void bulk_g2s(uint32_t dst_smem, const void* src_gmem,
                                         uint32_t bytes, uint32_t mbar) {
    asm volatile(
        "cp.async.bulk.shared::cta.global.mbarrier::complete_tx::bytes "
        "[%0], [%1], %2, [%3];"
        :: "r"(dst_smem), "l"(src_gmem), "r"(bytes), "r"(mbar) : "memory");
}

extern __shared__ float4 dynbuf[];   // conf: 5x20KB stages; sparse: keys

__global__ void __launch_bounds__(NTHREADS)
fused_kernel(const float* __restrict__ pred, const float* __restrict__ tg,
             int B, int N, int nconf, int nspb, int nblocks,
             float* __restrict__ out) {
    __shared__ uint64_t mbar_sto[NSTAGE];
    __shared__ int      swin[MAX_LOCAL];
    __shared__ float    shf[8];
    __shared__ float    shv[4][8];
    __shared__ int      s_ticket;

    const int tid  = threadIdx.x;
    const int bid  = blockIdx.x;
    const int lane = tid & 31, w = tid >> 5;

    if (bid < nconf) {
        // ======= conf block: whole plane prefetched at t0, 5 single-use stages
        int b = bid / NANCH;
        int a = bid - b * NANCH;
        const char* gsrc = (const char*)pred +
                           (size_t)(b * NCH + a * 8 + 4) * (size_t)PLANE_B;

        uint32_t sbase = smem_u32(dynbuf);
        uint32_t mb0   = smem_u32(&mbar_sto[0]);

        if (tid == 0) {
            #pragma unroll
            for (int s = 0; s < NSTAGE; ++s) mbar_init(mb0 + 8 * s, 1);
        }
        __syncthreads();                    // init visible before any wait
        if (tid == 0) {
            #pragma unroll
            for (int s = 0; s < NSTAGE; ++s) {
                mbar_expect_tx(mb0 + 8 * s, CHUNK_B);
                bulk_g2s(sbase + s * CHUNK_B, gsrc + s * CHUNK_B, CHUNK_B,
                         mb0 + 8 * s);
            }
        }

        float acc = 0.0f;
        #pragma unroll
        for (int c = 0; c < NSTAGE; ++c) {
            mbar_wait(mb0 + 8 * c, 0);      // single use, parity 0

            const float4* buf = dynbuf + c * CHUNK_F4 + tid;
            float4 v0 = buf[0];
            float4 v1 = buf[256];
            float4 v2 = buf[512];
            float4 v3 = buf[768];
            float4 v4 = buf[1024];
            float sg;
            #define SACC(x) { sg = sig_fast(x); acc = fmaf(sg, sg, acc); }
            SACC(v0.x) SACC(v0.y) SACC(v0.z) SACC(v0.w)
            SACC(v1.x) SACC(v1.y) SACC(v1.z) SACC(v1.w)
            SACC(v2.x) SACC(v2.y) SACC(v2.z) SACC(v2.w)
            SACC(v3.x) SACC(v3.y) SACC(v3.z) SACC(v3.w)
            SACC(v4.x) SACC(v4.y) SACC(v4.z) SACC(v4.w)
            #undef SACC
        }

        #pragma unroll
        for (int o = 16; o; o >>= 1) acc += __shfl_xor_sync(0xffffffffu, acc, o);
        if (lane == 0) shf[w] = acc;
        __syncthreads();
        if (tid == 0) {
            float t = 0.0f;
            #pragma unroll
            for (int i = 0; i < 8; ++i) t += shf[i];
            g_partials[bid] = t;
        }
    } else {
        // ======= sparse block (cooperative dedup, 1 thread per (t,a,ch)) =====
        int* keys = (int*)dynbuf;
        int nloc = (N < MAX_TGT) ? N : MAX_TGT;
        int sb   = bid - nconf;

        for (int t = tid; t < nloc; t += NTHREADS) {
            const float* r = tg + t * 6;
            int b  = (int)r[0];
            int gx = (int)(r[2] * (float)WID);
            int gy = (int)(r[3] * (float)HGT);
            bool valid = (gx >= 0) & (gx < WID) & (gy >= 0) & (gy < HGT) &
                         (b >= 0) & (b < B);
            keys[t] = valid ? (b * HW + gy * WID + gx) : -1;
        }
        if (tid < MAX_LOCAL) swin[tid] = 1;
        __syncthreads();

        int task_lo = sb * NTHREADS;
        int task_hi = task_lo + NTHREADS - 1;
        int ntask2  = nloc * NANCH * 8;
        if (task_hi >= ntask2) task_hi = ntask2 - 1;
        int t0 = task_lo / (NANCH * 8);
        int t1 = (task_hi >= task_lo) ? task_hi / (NANCH * 8) : t0 - 1;
        int nlocal = t1 - t0 + 1;

        if (nlocal > 0) {
            int nchunk = (nloc + 15) >> 4;
            int nitems = nlocal * nchunk;
            const int4* k4 = (const int4*)keys;
            for (int item = tid; item < nitems; item += NTHREADS) {
                int tl    = item / nchunk;
                int chunk = item - tl * nchunk;
                int t     = t0 + tl;
                int key   = keys[t];
                if (key < 0) continue;
                int jbase = chunk << 4;
                bool hit = false;
                #pragma unroll
                for (int q = 0; q < 4; ++q) {
                    int4 kk = k4[(jbase >> 2) + q];
                    int j = jbase + q * 4;
                    hit |= ((kk.x == key) & (j     > t) & (j     < nloc)) |
                           ((kk.y == key) & (j + 1 > t) & (j + 1 < nloc)) |
                           ((kk.z == key) & (j + 2 > t) & (j + 2 < nloc)) |
                           ((kk.w == key) & (j + 3 > t) & (j + 3 < nloc));
                }
                if (hit) swin[tl] = 0;      // benign race: same value
            }
        }
        __syncthreads();

        float sbox = 0.0f, scls = 0.0f, scorr = 0.0f, fcnt = 0.0f;

        int task2 = task_lo + tid;
        if (task2 < ntask2) {
            int ch   = task2 & 7;
            int task = task2 >> 3;
            int t = task / NANCH;
            int a = task - t * NANCH;
            int key = keys[t];
            if (key >= 0 && swin[t - t0]) {
                const float* r = tg + t * 6;
                int b = (int)r[0];
                int c = (int)r[1];
                int cell = key - b * HW;
                float p = pred[(size_t)(b * NCH + a * 8 + ch) * HW + cell];

                if (ch < 2) {
                    float d = sig_fast(p) - r[2 + ch];
                    sbox = d * d;
                } else if (ch < 4) {
                    float d = __expf(p) - r[2 + ch];
                    sbox = d * d;
                } else if (ch == 4) {
                    scorr = 1.0f - 2.0f * sig_fast(p);   // (s-1)^2 - s^2
                    fcnt  = 1.0f;
                } else {
                    float tt = ((ch - 5) == c) ? 1.0f : 0.0f;
                    float d  = sig_fast(p) - tt;
                    scls = d * d;
                }
            }
        }

        #pragma unroll
        for (int o = 16; o; o >>= 1) {
            sbox  += __shfl_xor_sync(0xffffffffu, sbox, o);
            scls  += __shfl_xor_sync(0xffffffffu, scls, o);
            scorr += __shfl_xor_sync(0xffffffffu, scorr, o);
            fcnt  += __shfl_xor_sync(0xffffffffu, fcnt, o);
        }
        if (lane == 0) {
            shv[0][w] = sbox; shv[1][w] = scls; shv[2][w] = scorr; shv[3][w] = fcnt;
        }
        __syncthreads();
        if (tid == 0) {
            float tb = 0, tc = 0, tr = 0, tn = 0;
            #pragma unroll
            for (int i = 0; i < 8; ++i) {
                tb += shv[0][i]; tc += shv[1][i]; tr += shv[2][i]; tn += shv[3][i];
            }
            g_sparse[sb][0] = tb;
            g_sparse[sb][1] = tc;
            g_sparse[sb][2] = tr;
            g_sparse[sb][3] = tn;
        }
    }

    // ============ last-arriving block folds everything =======================
    if (tid == 0) {
        __threadfence();
        s_ticket = atomicAdd(&g_count, 1);
    }
    __syncthreads();
    if (s_ticket != nblocks - 1) return;
    __threadfence();

    float sconf = 0.0f;
    if (tid < nconf) sconf = *(volatile float*)&g_partials[tid];

    float tb = 0, tc = 0, tr = 0, tn = 0;
    if (tid < nspb) {
        volatile float* rowp = &g_sparse[tid][0];
        tb = rowp[0]; tc = rowp[1]; tr = rowp[2]; tn = rowp[3];
    }

    #pragma unroll
    for (int o = 16; o; o >>= 1) {
        sconf += __shfl_xor_sync(0xffffffffu, sconf, o);
        tb    += __shfl_xor_sync(0xffffffffu, tb, o);
        tc    += __shfl_xor_sync(0xffffffffu, tc, o);
        tr    += __shfl_xor_sync(0xffffffffu, tr, o);
        tn    += __shfl_xor_sync(0xffffffffu, tn, o);
    }
    __syncthreads();
    if (lane == 0) {
        shf[w] = sconf;
        shv[0][w] = tb; shv[1][w] = tc; shv[2][w] = tr; shv[3][w] = tn;
    }
    __syncthreads();

    if (tid == 0) {
        float tf = 0, b2 = 0, c2 = 0, r2 = 0, n2 = 0;
        #pragma unroll
        for (int i = 0; i < 8; ++i) {
            tf += shf[i];
            b2 += shv[0][i]; c2 += shv[1][i]; r2 += shv[2][i]; n2 += shv[3][i];
        }
        float loss_box  = b2 / (n2 * 4.0f);
        float loss_cls  = c2 / (n2 * (float)NCLS);
        float total     = (float)B * (float)NANCH * (float)HW;
        float loss_conf = (tf + r2) / total;
        out[0] = 5.0f * loss_box + loss_conf + loss_cls;
        g_count = 0;   // reset for next graph replay
    }
}

extern "C" void kernel_launch(void* const* d_in, const int* in_sizes, int n_in,
                              void* d_out, int out_size) {
    const float* pred    = (const float*)d_in[0];
    const float* targets = (const float*)d_in[1];
    int B = in_sizes[0] / (NCH * HW);   // 32
    int N = in_sizes[1] / 6;            // 512
    float* out = (float*)d_out;

    int nconf  = B * NANCH;                            // 96
    int ntask2 = N * NANCH * 8;                        // 12288
    int nspb = (ntask2 + NTHREADS - 1) / NTHREADS;     // 48
    if (nspb > MAX_SPB) nspb = MAX_SPB;
    int nblocks = nconf + nspb;                        // 144

    cudaFuncSetAttribute(fused_kernel,
                         cudaFuncAttributeMaxDynamicSharedMemorySize, SMEM_DYN);
    fused_kernel<<<nblocks, NTHREADS, SMEM_DYN>>>(pred, targets, B, N,
                                                  nconf, nspb, nblocks, out);
}